// round 15
// baseline (speedup 1.0000x reference)
#include <cuda_runtime.h>
#include <cstdint>

#define NF   2
#define NLOC 4096
#define NNEI 64
#define NALL 6144
#define NG1  128
#define NG2  32
#define NH   4

// Folded weights: M_h = Wq_h Wk_h^T / sqrt(32), P_h = Wv_h @ Whm_h
__device__ __align__(16) float g_M[4 * 32 * 32];   // scratch (prep output)
__device__ __align__(16) float g_P[4 * 32 * 32];
__constant__ __align__(16) float c_M[4 * 32 * 32]; // const-port copies
__constant__ __align__(16) float c_P[4 * 32 * 32];

__global__ void prep_kernel(const float* __restrict__ wqk,
                            const float* __restrict__ wv,
                            const float* __restrict__ whm) {
    int t = threadIdx.x;  // 256 threads
    const float inv_sqrt_nd = 0.17677669529663689f;
    for (int i = 0; i < 16; ++i) {
        int idx = t + 256 * i;                 // [h][a][b]
        int h = idx >> 10, a = (idx >> 5) & 31, b = idx & 31;
        float s = 0.f;
        for (int d = 0; d < 32; ++d)
            s += wqk[a * 256 + d * 8 + h] * wqk[b * 256 + d * 8 + 4 + h];
        g_M[idx] = s * inv_sqrt_nd;
    }
    for (int i = 0; i < 16; ++i) {
        int idx = t + 256 * i;                 // [h][a][j]
        int h = idx >> 10, a = (idx >> 5) & 31, j = idx & 31;
        float s = 0.f;
        for (int c = 0; c < 32; ++c)
            s += wv[a * 128 + c * 4 + h] * whm[(c * 4 + h) * 32 + j];
        g_P[idx] = s;
    }
}

// packed f32x2 helpers
static __device__ __forceinline__ unsigned long long ffma2(
    unsigned long long a, unsigned long long b, unsigned long long c) {
    unsigned long long d;
    asm("fma.rn.f32x2 %0, %1, %2, %3;" : "=l"(d) : "l"(a), "l"(b), "l"(c));
    return d;
}
static __device__ __forceinline__ unsigned long long pack2(float lo, float hi) {
    unsigned long long d;
    asm("mov.b64 %0, {%1, %2};" : "=l"(d) : "f"(lo), "f"(hi));
    return d;
}
static __device__ __forceinline__ float2 unpack2(unsigned long long v) {
    float lo, hi;
    asm("mov.b64 {%0, %1}, %2;" : "=f"(lo), "=f"(hi) : "l"(v));
    return make_float2(lo, hi);
}

// Smem layout (float offsets) — 114576 B total, 2 CTAs/SM (proven)
#define OFF_G2U  0                       // [64][36]; cols 32..35 hold inv[row][h]
#define OFF_U    2304                    // [4][64][36]
#define OFF_AA   11520                   // [64][260]  (m-major; 260 = 4*65)
#define OFF_G2P  OFF_AA                  // [64][33]  ALIASED into AA (dead before phase 4)
#define OFF_H2   28160                   // [64][4]
#define OFF_SW   28416                   // [64]
#define OFF_MK   28480                   // [64]
#define OFF_BIAS 28544                   // [32]
#define OFF_WEV  28576                   // [4]
#define OFF_NLS  28580                   // [64] ints
#define SMEM_FLOATS 28644                // 114576 B

extern __shared__ float sm[];

__global__ void __launch_bounds__(256, 2)
repformer_kernel(const float* __restrict__ g1_ext,
                 const float* __restrict__ g2,
                 const float* __restrict__ h2,
                 const float* __restrict__ sw,
                 const float* __restrict__ bhm,
                 const float* __restrict__ wev_g,
                 const int* __restrict__ nlist,
                 const int* __restrict__ nmask,
                 float* __restrict__ out_gg1,
                 float* __restrict__ out_g2,
                 float* __restrict__ out_h2) {
    float* g2u  = sm + OFF_G2U;
    float* g2p  = sm + OFF_G2P;          // aliases AA region (phase 2 only)
    float* Us   = sm + OFF_U;
    float* AAs  = sm + OFF_AA;           // AA_un[m][h*64+row]
    float* h2s  = sm + OFF_H2;
    float* sws  = sm + OFF_SW;
    float* msk  = sm + OFF_MK;
    float* bias = sm + OFF_BIAS;
    float* wev  = sm + OFF_WEV;
    int*   nls  = (int*)(sm + OFF_NLS);

    const int t = threadIdx.x;
    const int tile = blockIdx.x;
    const int b = tile >> 12;

    // ---------------- Phase 1: stage tile inputs ----------------
    {
        const float4* g2g = (const float4*)(g2 + (size_t)tile * (NNEI * NG2));
        #pragma unroll
        for (int i = 0; i < 2; ++i) {
            int v = t + 256 * i;             // 512 float4
            float4 x = __ldg(&g2g[v]);
            int row = v >> 3, c4 = (v & 7) * 4;
            *(float4*)(g2u + row * 36 + c4) = x;
            float* r = g2p + row * 33 + c4;  // conflict-free scalar copy
            r[0] = x.x; r[1] = x.y; r[2] = x.z; r[3] = x.w;
        }
        if (t < 192) h2s[(t / 3) * 4 + (t % 3)] = __ldg(&h2[(size_t)tile * 192 + t]);
        if (t < 64) {
            h2s[t * 4 + 3] = 0.f;
            sws[t] = __ldg(&sw[(size_t)tile * 64 + t]);
            msk[t] = (__ldg(&nmask[(size_t)tile * 64 + t]) != 0) ? 1.f : 0.f;
            nls[t] = __ldg(&nlist[(size_t)tile * 64 + t]);
        }
        if (t < 32) bias[t] = __ldg(&bhm[t]);
        if (t < 4)  wev[t]  = __ldg(&wev_g[t]);
    }
    __syncthreads();

    if (t >= 128) {
        // ======== GATHER WARPS (4 warps): gg1, then phase 3 (U) ========
        const int tg = t - 128;
        {
            float4* dst = (float4*)(out_gg1 + (size_t)tile * (NNEI * NG1));
            const float4* src = (const float4*)(g1_ext + (size_t)b * NALL * NG1);
            #pragma unroll 4
            for (int i = 0; i < 16; ++i) {
                int v = tg + 128 * i;            // 2048 float4
                int nn = v >> 5, c4 = v & 31;
                float4 o;
                if (msk[nn] != 0.f) {
                    float sv = sws[nn];
                    float4 x = __ldg(&src[(size_t)nls[nn] * 32 + c4]);
                    o = make_float4(x.x * sv, x.y * sv, x.z * sv, x.w * sv);
                } else {
                    o = make_float4(0.f, 0.f, 0.f, 0.f);
                }
                dst[v] = o;
            }
        }
        // ---- Phase 3 (offloaded): U rows for heads hlo and hlo+2, row n ----
        {
            const int n   = tg & 63;
            const int hlo = tg >> 6;                 // 0 or 1
            const float* gr = g2u + n * 36;          // scalar reads (4-way conf ok)
            const ulonglong2* Plo = (const ulonglong2*)(c_P + hlo * 1024);
            const ulonglong2* Phi = (const ulonglong2*)(c_P + (hlo + 2) * 1024);
            unsigned long long UaA[16], UaB[16];
            #pragma unroll
            for (int i = 0; i < 16; ++i) { UaA[i] = 0ull; UaB[i] = 0ull; }
            for (int c = 0; c < 32; ++c) {
                float g = gr[c];
                unsigned long long gp = pack2(g, g);
                const ulonglong2* pr  = Plo + c * 8;
                const ulonglong2* pr2 = Phi + c * 8;
                #pragma unroll
                for (int q = 0; q < 8; ++q) {
                    ulonglong2 pv  = pr[q];
                    ulonglong2 pv2 = pr2[q];
                    UaA[q * 2]     = ffma2(gp, pv.x,  UaA[q * 2]);
                    UaA[q * 2 + 1] = ffma2(gp, pv.y,  UaA[q * 2 + 1]);
                    UaB[q * 2]     = ffma2(gp, pv2.x, UaB[q * 2]);
                    UaB[q * 2 + 1] = ffma2(gp, pv2.y, UaB[q * 2 + 1]);
                }
            }
            ulonglong2* udA = (ulonglong2*)(Us + (hlo * 64 + n) * 36);
            ulonglong2* udB = (ulonglong2*)(Us + ((hlo + 2) * 64 + n) * 36);
            #pragma unroll
            for (int q = 0; q < 8; ++q) {
                udA[q] = make_ulonglong2(UaA[q * 2], UaA[q * 2 + 1]);
                udB[q] = make_ulonglong2(UaB[q * 2], UaB[q * 2 + 1]);
            }
        }
    } else {
        // ============ COMPUTE WARPS (4 warps, 128 threads) ============
        const int h  = t >> 5;                   // head (one warp per head)
        const int n0 = t & 31;                   // rows n0 and n0+32
        const float* g2r0 = g2p + n0 * 33;       // conflict-free scalar reads
        const float* g2r1 = g2p + (n0 + 32) * 33;

        // -------- Phase 2: Tr = g2[n] @ M_h (const-port M reads) --------
        unsigned long long TrA[16], TrB[16];
        #pragma unroll
        for (int i = 0; i < 16; ++i) { TrA[i] = 0ull; TrB[i] = 0ull; }
        {
            const ulonglong2* M2 = (const ulonglong2*)(c_M + h * 1024);
            for (int c = 0; c < 32; ++c) {
                float ga = g2r0[c], gb = g2r1[c];
                unsigned long long gA = pack2(ga, ga), gB = pack2(gb, gb);
                const ulonglong2* mr = M2 + c * 8;
                #pragma unroll
                for (int q = 0; q < 8; ++q) {
                    ulonglong2 mv = mr[q];
                    TrA[q * 2]     = ffma2(gA, mv.x, TrA[q * 2]);
                    TrA[q * 2 + 1] = ffma2(gA, mv.y, TrA[q * 2 + 1]);
                    TrB[q * 2]     = ffma2(gB, mv.x, TrB[q * 2]);
                    TrB[q * 2 + 1] = ffma2(gB, mv.y, TrB[q * 2 + 1]);
                }
            }
        }

        // g2p dead among compute warps; AA region may be overwritten.
        asm volatile("bar.sync 1, 128;" ::: "memory");

        // ---- Phase 4: single-pass scores + exp (no max-sub; inv deferred) ----
        {
            float* arowA = AAs + h * 64 + n0;        // index by m*260
            float* arowB = AAs + h * 64 + n0 + 32;
            float4 hA = *(const float4*)(h2s + n0 * 4);
            float4 hB = *(const float4*)(h2s + (n0 + 32) * 4);
            float swA = sws[n0], swB = sws[n0 + 32];
            float sumA = 0.f, sumB = 0.f;

            for (int m4 = 0; m4 < 16; ++m4) {
                float4 sw4 = *(const float4*)(sws + m4 * 4);
                float4 mk4 = *(const float4*)(msk + m4 * 4);
                const float* swp = (const float*)&sw4;
                const float* mkp = (const float*)&mk4;
                #pragma unroll
                for (int mi = 0; mi < 4; ++mi) {
                    int m = m4 * 4 + mi;
                    const ulonglong2* gm = (const ulonglong2*)(g2u + m * 36);
                    unsigned long long aA0 = 0ull, aA1 = 0ull, aB0 = 0ull, aB1 = 0ull;
                    #pragma unroll
                    for (int q = 0; q < 8; ++q) {
                        ulonglong2 gv = gm[q];
                        aA0 = ffma2(TrA[q * 2],     gv.x, aA0);
                        aA1 = ffma2(TrA[q * 2 + 1], gv.y, aA1);
                        aB0 = ffma2(TrB[q * 2],     gv.x, aB0);
                        aB1 = ffma2(TrB[q * 2 + 1], gv.y, aB1);
                    }
                    float2 uA0 = unpack2(aA0), uA1 = unpack2(aA1);
                    float2 uB0 = unpack2(aB0), uB1 = unpack2(aB1);
                    float accA = (uA0.x + uA0.y) + (uA1.x + uA1.y);
                    float accB = (uB0.x + uB0.y) + (uB1.x + uB1.y);
                    float4 hm = *(const float4*)(h2s + m * 4);
                    float swm = swp[mi], mm = mkp[mi];
                    float gateA = hA.x * hm.x + hA.y * hm.y + hA.z * hm.z;
                    float gateB = hB.x * hm.x + hB.y * hm.y + hB.z * hm.z;
                    float sw2A = swA * swm, sw2B = swB * swm;
                    float sA = (accA * gateA + 20.f) * sw2A - 20.f;
                    float sB = (accB * gateB + 20.f) * sw2B - 20.f;
                    float eA = __expf(sA), eB = __expf(sB);
                    sumA += eA; sumB += eB;
                    arowA[m * 260] = eA * (gateA * sw2A * mm);
                    arowB[m * 260] = eB * (gateB * sw2B * mm);
                }
            }
            float invA = msk[n0]      * 0.5773502691896258f / sumA;
            float invB = msk[n0 + 32] * 0.5773502691896258f / sumB;
            g2u[n0 * 36 + 32 + h]        = invA;   // stash in g2u padding
            g2u[(n0 + 32) * 36 + 32 + h] = invB;
        }
    }

    __syncthreads();   // AA + U + inv all published

    // ---------------- Phase 6 (ALL 256 threads): 4 rows x 2 cols / thread ----------------
    {
        const int rowg = t >> 4;             // 0..15 -> rows rowg*4 .. +3
        const int jg2  = t & 15;             // 0..15 -> cols jg2*2, jg2*2+1
        const int r0 = rowg * 4;
        unsigned long long cc[4];
        #pragma unroll
        for (int i = 0; i < 4; ++i) cc[i] = 0ull;
        float hx[4][3];
        #pragma unroll
        for (int ri = 0; ri < 4; ++ri) { hx[ri][0] = hx[ri][1] = hx[ri][2] = 0.f; }
        const float w0 = wev[0], w1 = wev[1], w2 = wev[2], w3 = wev[3];

        // per-thread normalizers inv[hh][ri] from g2u padding
        float iv[4][4];
        #pragma unroll
        for (int hh = 0; hh < 4; ++hh)
            #pragma unroll
            for (int ri = 0; ri < 4; ++ri)
                iv[hh][ri] = g2u[(r0 + ri) * 36 + 32 + hh];

        for (int m = 0; m < 64; ++m) {
            float4 av[4];
            #pragma unroll
            for (int hh = 0; hh < 4; ++hh)
                av[hh] = *(const float4*)(AAs + m * 260 + hh * 64 + r0);
            const float* araw = (const float*)av;   // araw[hh*4 + ri] (unnormalized)
            float a[16];
            #pragma unroll
            for (int hh = 0; hh < 4; ++hh)
                #pragma unroll
                for (int ri = 0; ri < 4; ++ri)
                    a[hh * 4 + ri] = araw[hh * 4 + ri] * iv[hh][ri];
            #pragma unroll
            for (int hh = 0; hh < 4; ++hh) {
                unsigned long long up =
                    *(const unsigned long long*)(Us + (hh * 64 + m) * 36 + jg2 * 2);
                #pragma unroll
                for (int ri = 0; ri < 4; ++ri) {
                    unsigned long long aa = pack2(a[hh * 4 + ri], a[hh * 4 + ri]);
                    cc[ri] = ffma2(aa, up, cc[ri]);
                }
            }
            if ((m >> 2) == jg2) {           // partition m over the 16 jg2 lanes
                float4 hm = *(const float4*)(h2s + m * 4);
                #pragma unroll
                for (int ri = 0; ri < 4; ++ri) {
                    float aw = a[0 * 4 + ri] * w0 + a[1 * 4 + ri] * w1 +
                               a[2 * 4 + ri] * w2 + a[3 * 4 + ri] * w3;
                    hx[ri][0] += aw * hm.x;
                    hx[ri][1] += aw * hm.y;
                    hx[ri][2] += aw * hm.z;
                }
            }
        }
        // reduce h2_out partials over the 16 jg2 lanes
        #pragma unroll
        for (int d = 1; d < 16; d <<= 1)
            #pragma unroll
            for (int ri = 0; ri < 4; ++ri) {
                hx[ri][0] += __shfl_xor_sync(0xffffffffu, hx[ri][0], d);
                hx[ri][1] += __shfl_xor_sync(0xffffffffu, hx[ri][1], d);
                hx[ri][2] += __shfl_xor_sync(0xffffffffu, hx[ri][2], d);
            }
        if (jg2 == 0) {
            #pragma unroll
            for (int ri = 0; ri < 4; ++ri) {
                float* ho = out_h2 + (size_t)tile * 192 + (r0 + ri) * 3;
                ho[0] = hx[ri][0]; ho[1] = hx[ri][1]; ho[2] = hx[ri][2];
            }
        }
        float2 bi = *(const float2*)(bias + jg2 * 2);
        #pragma unroll
        for (int ri = 0; ri < 4; ++ri) {
            float2 c0 = unpack2(cc[ri]);
            *(float2*)(out_g2 + ((size_t)tile * 64 + r0 + ri) * 32 + jg2 * 2) =
                make_float2(c0.x + bi.x, c0.y + bi.y);
        }
    }
}

extern "C" void kernel_launch(void* const* d_in, const int* in_sizes, int n_in,
                              void* d_out, int out_size) {
    (void)in_sizes; (void)n_in; (void)out_size;
    const float* g1_ext = (const float*)d_in[0];
    const float* g2     = (const float*)d_in[1];
    const float* h2     = (const float*)d_in[2];
    const float* sw     = (const float*)d_in[3];
    const float* wqk    = (const float*)d_in[4];
    const float* wv     = (const float*)d_in[5];
    const float* whm    = (const float*)d_in[6];
    const float* bhm    = (const float*)d_in[7];
    const float* wev    = (const float*)d_in[8];
    const int* nlist    = (const int*)d_in[9];
    const int* nmask    = (const int*)d_in[10];

    float* out = (float*)d_out;
    float* out_gg1 = out;
    float* out_g2  = out + 67108864ll;
    float* out_h2  = out + 83886080ll;

    size_t smem = SMEM_FLOATS * sizeof(float);   // 114576 B -> 2 CTAs/SM
    cudaFuncSetAttribute(repformer_kernel,
                         cudaFuncAttributeMaxDynamicSharedMemorySize, (int)smem);

    prep_kernel<<<1, 256>>>(wqk, wv, whm);

    // Move folded weights to constant space (D2D memcpy nodes; graph-capturable)
    void* pM = nullptr; void* pP = nullptr;
    cudaGetSymbolAddress(&pM, g_M);
    cudaGetSymbolAddress(&pP, g_P);
    cudaMemcpyToSymbolAsync(c_M, pM, 4 * 32 * 32 * sizeof(float), 0,
                            cudaMemcpyDeviceToDevice, 0);
    cudaMemcpyToSymbolAsync(c_P, pP, 4 * 32 * 32 * sizeof(float), 0,
                            cudaMemcpyDeviceToDevice, 0);

    repformer_kernel<<<NF * NLOC, 256, smem>>>(
        g1_ext, g2, h2, sw, bhm, wev, nlist, nmask,
        out_gg1, out_g2, out_h2);
}

// round 17
// speedup vs baseline: 1.1178x; 1.1178x over previous
#include <cuda_runtime.h>
#include <cstdint>

#define NF   2
#define NLOC 4096
#define NNEI 64
#define NALL 6144
#define NG1  128
#define NG2  32
#define NH   4

// Folded weights: M_h = Wq_h Wk_h^T / sqrt(32), P_h = Wv_h @ Whm_h
__device__ __align__(16) float g_M[4 * 32 * 32];   // scratch (prep output)
__device__ __align__(16) float g_P[4 * 32 * 32];
__constant__ __align__(16) float c_M[4 * 32 * 32]; // const-port copies
__constant__ __align__(16) float c_P[4 * 32 * 32];

__global__ void prep_kernel(const float* __restrict__ wqk,
                            const float* __restrict__ wv,
                            const float* __restrict__ whm) {
    int t = threadIdx.x;  // 256 threads
    const float inv_sqrt_nd = 0.17677669529663689f;
    for (int i = 0; i < 16; ++i) {
        int idx = t + 256 * i;                 // [h][a][b]
        int h = idx >> 10, a = (idx >> 5) & 31, b = idx & 31;
        float s = 0.f;
        for (int d = 0; d < 32; ++d)
            s += wqk[a * 256 + d * 8 + h] * wqk[b * 256 + d * 8 + 4 + h];
        g_M[idx] = s * inv_sqrt_nd;
    }
    for (int i = 0; i < 16; ++i) {
        int idx = t + 256 * i;                 // [h][a][j]
        int h = idx >> 10, a = (idx >> 5) & 31, j = idx & 31;
        float s = 0.f;
        for (int c = 0; c < 32; ++c)
            s += wv[a * 128 + c * 4 + h] * whm[(c * 4 + h) * 32 + j];
        g_P[idx] = s;
    }
}

// packed f32x2 helpers
static __device__ __forceinline__ unsigned long long ffma2(
    unsigned long long a, unsigned long long b, unsigned long long c) {
    unsigned long long d;
    asm("fma.rn.f32x2 %0, %1, %2, %3;" : "=l"(d) : "l"(a), "l"(b), "l"(c));
    return d;
}
static __device__ __forceinline__ unsigned long long pack2(float lo, float hi) {
    unsigned long long d;
    asm("mov.b64 %0, {%1, %2};" : "=l"(d) : "f"(lo), "f"(hi));
    return d;
}
static __device__ __forceinline__ float2 unpack2(unsigned long long v) {
    float lo, hi;
    asm("mov.b64 {%0, %1}, %2;" : "=f"(lo), "=f"(hi) : "l"(v));
    return make_float2(lo, hi);
}

// Smem layout (float offsets) — 114576 B total, 2 CTAs/SM (proven)
#define OFF_G2U  0                       // [64][36]; cols 32..35 hold inv[row][h]
#define OFF_U    2304                    // [4][64][36]
#define OFF_AA   11520                   // [64][260]  (m-major; 260 = 4*65)
#define OFF_G2P  OFF_AA                  // [64][33]  ALIASED into AA (dead before phase 4)
#define OFF_H2   28160                   // [64][4]
#define OFF_SW   28416                   // [64]
#define OFF_MK   28480                   // [64]
#define OFF_BIAS 28544                   // [32]
#define OFF_WEV  28576                   // [4]
#define OFF_NLS  28580                   // [64] ints
#define SMEM_FLOATS 28644                // 114576 B

extern __shared__ float sm[];

__global__ void __launch_bounds__(256, 2)
repformer_kernel(const float* __restrict__ g1_ext,
                 const float* __restrict__ g2,
                 const float* __restrict__ h2,
                 const float* __restrict__ sw,
                 const float* __restrict__ bhm,
                 const float* __restrict__ wev_g,
                 const int* __restrict__ nlist,
                 const int* __restrict__ nmask,
                 float* __restrict__ out_gg1,
                 float* __restrict__ out_g2,
                 float* __restrict__ out_h2) {
    float* g2u  = sm + OFF_G2U;
    float* g2p  = sm + OFF_G2P;          // aliases AA region (phase 2 only)
    float* Us   = sm + OFF_U;
    float* AAs  = sm + OFF_AA;           // AA_un[m][h*64+row]
    float* h2s  = sm + OFF_H2;
    float* sws  = sm + OFF_SW;
    float* msk  = sm + OFF_MK;
    float* bias = sm + OFF_BIAS;
    float* wev  = sm + OFF_WEV;
    int*   nls  = (int*)(sm + OFF_NLS);

    const int t = threadIdx.x;
    const int tile = blockIdx.x;
    const int b = tile >> 12;

    // ---------------- Phase 1: stage tile inputs ----------------
    {
        const float4* g2g = (const float4*)(g2 + (size_t)tile * (NNEI * NG2));
        #pragma unroll
        for (int i = 0; i < 2; ++i) {
            int v = t + 256 * i;             // 512 float4
            float4 x = __ldg(&g2g[v]);
            int row = v >> 3, c4 = (v & 7) * 4;
            *(float4*)(g2u + row * 36 + c4) = x;
            float* r = g2p + row * 33 + c4;  // conflict-free scalar copy
            r[0] = x.x; r[1] = x.y; r[2] = x.z; r[3] = x.w;
        }
        if (t < 192) h2s[(t / 3) * 4 + (t % 3)] = __ldg(&h2[(size_t)tile * 192 + t]);
        if (t < 64) {
            h2s[t * 4 + 3] = 0.f;
            sws[t] = __ldg(&sw[(size_t)tile * 64 + t]);
            msk[t] = (__ldg(&nmask[(size_t)tile * 64 + t]) != 0) ? 1.f : 0.f;
            nls[t] = __ldg(&nlist[(size_t)tile * 64 + t]);
        }
        if (t < 32) bias[t] = __ldg(&bhm[t]);
        if (t < 4)  wev[t]  = __ldg(&wev_g[t]);
    }
    __syncthreads();

    if (t >= 128) {
        // ======== GATHER WARPS (4 warps): gg1, then phase 3 (U) ========
        const int tg = t - 128;
        {
            float4* dst = (float4*)(out_gg1 + (size_t)tile * (NNEI * NG1));
            const float4* src = (const float4*)(g1_ext + (size_t)b * NALL * NG1);
            #pragma unroll 4
            for (int i = 0; i < 16; ++i) {
                int v = tg + 128 * i;            // 2048 float4
                int nn = v >> 5, c4 = v & 31;
                float4 o;
                if (msk[nn] != 0.f) {
                    float sv = sws[nn];
                    float4 x = __ldg(&src[(size_t)nls[nn] * 32 + c4]);
                    o = make_float4(x.x * sv, x.y * sv, x.z * sv, x.w * sv);
                } else {
                    o = make_float4(0.f, 0.f, 0.f, 0.f);
                }
                dst[v] = o;
            }
        }
        // ---- Phase 3 (offloaded): U rows for heads hlo and hlo+2, row n ----
        {
            const int n   = tg & 63;
            const int hlo = tg >> 6;                 // 0 or 1
            const float* gr = g2u + n * 36;          // scalar reads (4-way conf ok)
            const ulonglong2* Plo = (const ulonglong2*)(c_P + hlo * 1024);
            const ulonglong2* Phi = (const ulonglong2*)(c_P + (hlo + 2) * 1024);
            unsigned long long UaA[16], UaB[16];
            #pragma unroll
            for (int i = 0; i < 16; ++i) { UaA[i] = 0ull; UaB[i] = 0ull; }
            for (int c = 0; c < 32; ++c) {
                float g = gr[c];
                unsigned long long gp = pack2(g, g);
                const ulonglong2* pr  = Plo + c * 8;
                const ulonglong2* pr2 = Phi + c * 8;
                #pragma unroll
                for (int q = 0; q < 8; ++q) {
                    ulonglong2 pv  = pr[q];
                    ulonglong2 pv2 = pr2[q];
                    UaA[q * 2]     = ffma2(gp, pv.x,  UaA[q * 2]);
                    UaA[q * 2 + 1] = ffma2(gp, pv.y,  UaA[q * 2 + 1]);
                    UaB[q * 2]     = ffma2(gp, pv2.x, UaB[q * 2]);
                    UaB[q * 2 + 1] = ffma2(gp, pv2.y, UaB[q * 2 + 1]);
                }
            }
            ulonglong2* udA = (ulonglong2*)(Us + (hlo * 64 + n) * 36);
            ulonglong2* udB = (ulonglong2*)(Us + ((hlo + 2) * 64 + n) * 36);
            #pragma unroll
            for (int q = 0; q < 8; ++q) {
                udA[q] = make_ulonglong2(UaA[q * 2], UaA[q * 2 + 1]);
                udB[q] = make_ulonglong2(UaB[q * 2], UaB[q * 2 + 1]);
            }
        }
        asm volatile("bar.sync 0, 256;" ::: "memory");  // publish U
        return;
    }

    // ============ COMPUTE WARPS (4 warps, 128 threads) ============
    const int h  = t >> 5;                   // head (one warp per head)
    const int n0 = t & 31;                   // rows n0 and n0+32
    const float* g2r0 = g2p + n0 * 33;       // conflict-free scalar reads
    const float* g2r1 = g2p + (n0 + 32) * 33;

    // ---------------- Phase 2: Tr = g2[n] @ M_h (const-port M reads) ----------------
    unsigned long long TrA[16], TrB[16];
    #pragma unroll
    for (int i = 0; i < 16; ++i) { TrA[i] = 0ull; TrB[i] = 0ull; }
    {
        const ulonglong2* M2 = (const ulonglong2*)(c_M + h * 1024);
        for (int c = 0; c < 32; ++c) {
            float ga = g2r0[c], gb = g2r1[c];
            unsigned long long gA = pack2(ga, ga), gB = pack2(gb, gb);
            const ulonglong2* mr = M2 + c * 8;
            #pragma unroll
            for (int q = 0; q < 8; ++q) {
                ulonglong2 mv = mr[q];
                TrA[q * 2]     = ffma2(gA, mv.x, TrA[q * 2]);
                TrA[q * 2 + 1] = ffma2(gA, mv.y, TrA[q * 2 + 1]);
                TrB[q * 2]     = ffma2(gB, mv.x, TrB[q * 2]);
                TrB[q * 2 + 1] = ffma2(gB, mv.y, TrB[q * 2 + 1]);
            }
        }
    }

    // g2p dead among compute warps; AA region may be overwritten.
    asm volatile("bar.sync 1, 128;" ::: "memory");

    // ---- Phase 4: single-pass scores + exp (no max-sub; inv deferred) ----
    {
        float* arowA = AAs + h * 64 + n0;        // index by m*260
        float* arowB = AAs + h * 64 + n0 + 32;
        float4 hA = *(const float4*)(h2s + n0 * 4);
        float4 hB = *(const float4*)(h2s + (n0 + 32) * 4);
        float swA = sws[n0], swB = sws[n0 + 32];
        float sumA = 0.f, sumB = 0.f;

        for (int m4 = 0; m4 < 16; ++m4) {
            // batch all loads for this 4-m group up front (MLP)
            float4 sw4 = *(const float4*)(sws + m4 * 4);
            float4 mk4 = *(const float4*)(msk + m4 * 4);
            float4 hm4[4];
            #pragma unroll
            for (int mi = 0; mi < 4; ++mi)
                hm4[mi] = *(const float4*)(h2s + (m4 * 4 + mi) * 4);
            const float* swp = (const float*)&sw4;
            const float* mkp = (const float*)&mk4;
            #pragma unroll
            for (int mi = 0; mi < 4; ++mi) {
                int m = m4 * 4 + mi;
                const ulonglong2* gm = (const ulonglong2*)(g2u + m * 36);
                ulonglong2 gv0 = gm[0], gv1 = gm[1], gv2 = gm[2], gv3 = gm[3];
                ulonglong2 gv4 = gm[4], gv5 = gm[5], gv6 = gm[6], gv7 = gm[7];
                unsigned long long aA0 = 0ull, aA1 = 0ull, aB0 = 0ull, aB1 = 0ull;
                aA0 = ffma2(TrA[0],  gv0.x, aA0); aA1 = ffma2(TrA[1],  gv0.y, aA1);
                aB0 = ffma2(TrB[0],  gv0.x, aB0); aB1 = ffma2(TrB[1],  gv0.y, aB1);
                aA0 = ffma2(TrA[2],  gv1.x, aA0); aA1 = ffma2(TrA[3],  gv1.y, aA1);
                aB0 = ffma2(TrB[2],  gv1.x, aB0); aB1 = ffma2(TrB[3],  gv1.y, aB1);
                aA0 = ffma2(TrA[4],  gv2.x, aA0); aA1 = ffma2(TrA[5],  gv2.y, aA1);
                aB0 = ffma2(TrB[4],  gv2.x, aB0); aB1 = ffma2(TrB[5],  gv2.y, aB1);
                aA0 = ffma2(TrA[6],  gv3.x, aA0); aA1 = ffma2(TrA[7],  gv3.y, aA1);
                aB0 = ffma2(TrB[6],  gv3.x, aB0); aB1 = ffma2(TrB[7],  gv3.y, aB1);
                aA0 = ffma2(TrA[8],  gv4.x, aA0); aA1 = ffma2(TrA[9],  gv4.y, aA1);
                aB0 = ffma2(TrB[8],  gv4.x, aB0); aB1 = ffma2(TrB[9],  gv4.y, aB1);
                aA0 = ffma2(TrA[10], gv5.x, aA0); aA1 = ffma2(TrA[11], gv5.y, aA1);
                aB0 = ffma2(TrB[10], gv5.x, aB0); aB1 = ffma2(TrB[11], gv5.y, aB1);
                aA0 = ffma2(TrA[12], gv6.x, aA0); aA1 = ffma2(TrA[13], gv6.y, aA1);
                aB0 = ffma2(TrB[12], gv6.x, aB0); aB1 = ffma2(TrB[13], gv6.y, aB1);
                aA0 = ffma2(TrA[14], gv7.x, aA0); aA1 = ffma2(TrA[15], gv7.y, aA1);
                aB0 = ffma2(TrB[14], gv7.x, aB0); aB1 = ffma2(TrB[15], gv7.y, aB1);
                float2 uA0 = unpack2(aA0), uA1 = unpack2(aA1);
                float2 uB0 = unpack2(aB0), uB1 = unpack2(aB1);
                float accA = (uA0.x + uA0.y) + (uA1.x + uA1.y);
                float accB = (uB0.x + uB0.y) + (uB1.x + uB1.y);
                float4 hm = hm4[mi];
                float swm = swp[mi], mm = mkp[mi];
                float gateA = hA.x * hm.x + hA.y * hm.y + hA.z * hm.z;
                float gateB = hB.x * hm.x + hB.y * hm.y + hB.z * hm.z;
                float sw2A = swA * swm, sw2B = swB * swm;
                float sA = (accA * gateA + 20.f) * sw2A - 20.f;
                float sB = (accB * gateB + 20.f) * sw2B - 20.f;
                float eA = __expf(sA), eB = __expf(sB);
                sumA += eA; sumB += eB;
                arowA[m * 260] = eA * (gateA * sw2A * mm);
                arowB[m * 260] = eB * (gateB * sw2B * mm);
            }
        }
        float invA = msk[n0]      * 0.5773502691896258f / sumA;
        float invB = msk[n0 + 32] * 0.5773502691896258f / sumB;
        g2u[n0 * 36 + 32 + h]        = invA;   // stash in g2u padding
        g2u[(n0 + 32) * 36 + 32 + h] = invB;
    }

    asm volatile("bar.sync 0, 256;" ::: "memory");  // AA ready + U from gather warps

    // ---------------- Phase 6 (128 threads): 4 rows x 4 cols / thread ----------------
    {
        const int rowg = t >> 3;             // 0..15  -> rows rowg*4 .. +3
        const int jg   = t & 7;              // 0..7   -> cols jg*4 .. +3
        const int r0 = rowg * 4;
        unsigned long long cc[8];
        #pragma unroll
        for (int i = 0; i < 8; ++i) cc[i] = 0ull;
        float hx[4][3];
        #pragma unroll
        for (int ri = 0; ri < 4; ++ri) { hx[ri][0] = hx[ri][1] = hx[ri][2] = 0.f; }
        const float w0 = wev[0], w1 = wev[1], w2 = wev[2], w3 = wev[3];

        // per-thread normalizers inv[hh][ri] from g2u padding
        float iv[4][4];
        #pragma unroll
        for (int hh = 0; hh < 4; ++hh)
            #pragma unroll
            for (int ri = 0; ri < 4; ++ri)
                iv[hh][ri] = g2u[(r0 + ri) * 36 + 32 + hh];

        #pragma unroll 2
        for (int mm2 = 0; mm2 < 32; ++mm2) {
            // software pipeline: batch loads for m = 2*mm2 and 2*mm2+1
            const int m0 = mm2 * 2, m1 = m0 + 1;
            float4 av0[4], av1[4];
            ulonglong2 up0[4], up1[4];
            #pragma unroll
            for (int hh = 0; hh < 4; ++hh) {
                av0[hh] = *(const float4*)(AAs + m0 * 260 + hh * 64 + r0);
                av1[hh] = *(const float4*)(AAs + m1 * 260 + hh * 64 + r0);
                up0[hh] = *(const ulonglong2*)(Us + (hh * 64 + m0) * 36 + jg * 4);
                up1[hh] = *(const ulonglong2*)(Us + (hh * 64 + m1) * 36 + jg * 4);
            }
            #pragma unroll
            for (int half = 0; half < 2; ++half) {
                const int m = half ? m1 : m0;
                const float4* avp = half ? av1 : av0;
                const ulonglong2* upp = half ? up1 : up0;
                const float* araw = (const float*)avp;   // araw[hh*4 + ri]
                float a[16];
                #pragma unroll
                for (int hh = 0; hh < 4; ++hh)
                    #pragma unroll
                    for (int ri = 0; ri < 4; ++ri)
                        a[hh * 4 + ri] = araw[hh * 4 + ri] * iv[hh][ri];
                #pragma unroll
                for (int hh = 0; hh < 4; ++hh) {
                    ulonglong2 up = upp[hh];
                    #pragma unroll
                    for (int ri = 0; ri < 4; ++ri) {
                        unsigned long long aa = pack2(a[hh * 4 + ri], a[hh * 4 + ri]);
                        cc[ri * 2]     = ffma2(aa, up.x, cc[ri * 2]);
                        cc[ri * 2 + 1] = ffma2(aa, up.y, cc[ri * 2 + 1]);
                    }
                }
                if ((m >> 3) == jg) {            // partition m over jg for h2_out
                    float4 hm = *(const float4*)(h2s + m * 4);
                    #pragma unroll
                    for (int ri = 0; ri < 4; ++ri) {
                        float aw = a[0 * 4 + ri] * w0 + a[1 * 4 + ri] * w1 +
                                   a[2 * 4 + ri] * w2 + a[3 * 4 + ri] * w3;
                        hx[ri][0] += aw * hm.x;
                        hx[ri][1] += aw * hm.y;
                        hx[ri][2] += aw * hm.z;
                    }
                }
            }
        }
        // reduce h2_out partials over the 8 jg lanes
        #pragma unroll
        for (int d = 1; d < 8; d <<= 1)
            #pragma unroll
            for (int ri = 0; ri < 4; ++ri) {
                hx[ri][0] += __shfl_xor_sync(0xffffffffu, hx[ri][0], d);
                hx[ri][1] += __shfl_xor_sync(0xffffffffu, hx[ri][1], d);
                hx[ri][2] += __shfl_xor_sync(0xffffffffu, hx[ri][2], d);
            }
        if (jg == 0) {
            #pragma unroll
            for (int ri = 0; ri < 4; ++ri) {
                float* ho = out_h2 + (size_t)tile * 192 + (r0 + ri) * 3;
                ho[0] = hx[ri][0]; ho[1] = hx[ri][1]; ho[2] = hx[ri][2];
            }
        }
        float4 bi = *(const float4*)(bias + jg * 4);
        #pragma unroll
        for (int ri = 0; ri < 4; ++ri) {
            float2 c0 = unpack2(cc[ri * 2]), c1 = unpack2(cc[ri * 2 + 1]);
            float4 o = make_float4(c0.x + bi.x, c0.y + bi.y, c1.x + bi.z, c1.y + bi.w);
            *(float4*)(out_g2 + ((size_t)tile * 64 + r0 + ri) * 32 + jg * 4) = o;
        }
    }
}

extern "C" void kernel_launch(void* const* d_in, const int* in_sizes, int n_in,
                              void* d_out, int out_size) {
    (void)in_sizes; (void)n_in; (void)out_size;
    const float* g1_ext = (const float*)d_in[0];
    const float* g2     = (const float*)d_in[1];
    const float* h2     = (const float*)d_in[2];
    const float* sw     = (const float*)d_in[3];
    const float* wqk    = (const float*)d_in[4];
    const float* wv     = (const float*)d_in[5];
    const float* whm    = (const float*)d_in[6];
    const float* bhm    = (const float*)d_in[7];
    const float* wev    = (const float*)d_in[8];
    const int* nlist    = (const int*)d_in[9];
    const int* nmask    = (const int*)d_in[10];

    float* out = (float*)d_out;
    float* out_gg1 = out;
    float* out_g2  = out + 67108864ll;
    float* out_h2  = out + 83886080ll;

    size_t smem = SMEM_FLOATS * sizeof(float);   // 114576 B -> 2 CTAs/SM
    cudaFuncSetAttribute(repformer_kernel,
                         cudaFuncAttributeMaxDynamicSharedMemorySize, (int)smem);

    prep_kernel<<<1, 256>>>(wqk, wv, whm);

    // Move folded weights to constant space (D2D memcpy nodes; graph-capturable)
    void* pM = nullptr; void* pP = nullptr;
    cudaGetSymbolAddress(&pM, g_M);
    cudaGetSymbolAddress(&pP, g_P);
    cudaMemcpyToSymbolAsync(c_M, pM, 4 * 32 * 32 * sizeof(float), 0,
                            cudaMemcpyDeviceToDevice, 0);
    cudaMemcpyToSymbolAsync(c_P, pP, 4 * 32 * 32 * sizeof(float), 0,
                            cudaMemcpyDeviceToDevice, 0);

    repformer_kernel<<<NF * NLOC, 256, smem>>>(
        g1_ext, g2, h2, sw, bhm, wev, nlist, nmask,
        out_gg1, out_g2, out_h2);
}